// round 6
// baseline (speedup 1.0000x reference)
#include <cuda_runtime.h>
#include <math.h>

// Problem constants (match reference)
#define B_ 2
#define H_ 512
#define W_ 512
#define D_ 128
#define NSTEPS 180
#define NPIX (B_ * H_ * W_)
#define NVOX (D_ * D_ * D_)

// Output packing: [rgb (B,3,H,W)][alpha (B,1,H,W)][length (B,1,H,W)]
#define A_OFF (B_ * 3 * H_ * W_)
#define L_OFF (A_OFF + NPIX)

// ---------------- device scratch (static allocations only) ----------------
__device__ float4 g_grid[(size_t)B_ * NVOX];     // AoS repacked template (~67MB, L2-resident)
__device__ uint4 g_keys8[(NSTEPS + 1) * 2];      // per-step folded threefry key schedule
__device__ unsigned g_minb, g_maxb;              // global min/max of raw ray_length (uint-punned)

__device__ __forceinline__ float ex2f(float x) {
  float r;
  asm("ex2.approx.f32 %0, %1;" : "=f"(r) : "f"(x));
  return r;
}
__device__ __forceinline__ float lg2f(float x) {
  float r;
  asm("lg2.approx.f32 %0, %1;" : "=f"(r) : "f"(x));
  return r;
}
__device__ __forceinline__ float sqrt_ap(float x) {
  float r;
  asm("sqrt.approx.f32 %0, %1;" : "=f"(r) : "f"(x));
  return r;
}

// ---------------- threefry2x32 (reference block, host-side key schedule) ----------------
__device__ __forceinline__ void tf_block(unsigned k0, unsigned k1, unsigned x0, unsigned x1,
                                         unsigned& o0, unsigned& o1) {
  unsigned k2 = k0 ^ k1 ^ 0x1BD11BDAu;
#define TF_R(r) { x0 += x1; x1 = (x1 << (r)) | (x1 >> (32 - (r))); x1 ^= x0; }
  x0 += k0; x1 += k1;
  TF_R(13) TF_R(15) TF_R(26) TF_R(6)
  x0 += k1; x1 += k2 + 1u;
  TF_R(17) TF_R(29) TF_R(16) TF_R(24)
  x0 += k2; x1 += k0 + 2u;
  TF_R(13) TF_R(15) TF_R(26) TF_R(6)
  x0 += k0; x1 += k1 + 3u;
  TF_R(17) TF_R(29) TF_R(16) TF_R(24)
  x0 += k1; x1 += k2 + 4u;
  TF_R(13) TF_R(15) TF_R(26) TF_R(6)
  x0 += k2; x1 += k0 + 5u;
#undef TF_R
  o0 = x0; o1 = x1;
}

// threefry with precomputed key schedule: a = {k0,k1,k2,k2+1}, b = {k0+2,k1+3,k2+4,k0+5}
// counter = (hi=0, lo=p); returns o0 ^ o1 (partitionable fold). Key injections fused
// into the following round's add (3-input IADD3).
__device__ __forceinline__ unsigned rbits8(uint4 a, uint4 b, unsigned p) {
#define TF_R(r)  { x0 += x1; x1 = __funnelshift_l(x1, x1, (r)); x1 ^= x0; }
  unsigned x1 = p + a.y;              // p + k1
  unsigned x0 = a.x + x1;             // (0 + k0) + x1  [round 1 add]
  x1 = __funnelshift_l(x1, x1, 13); x1 ^= x0;
  TF_R(15) TF_R(26) TF_R(6)
  x1 += a.w; x0 += a.y + x1;          // inject (k1, k2+1) fused with round add
  x1 = __funnelshift_l(x1, x1, 17); x1 ^= x0;
  TF_R(29) TF_R(16) TF_R(24)
  x1 += b.x; x0 += a.z + x1;          // inject (k2, k0+2)
  x1 = __funnelshift_l(x1, x1, 13); x1 ^= x0;
  TF_R(15) TF_R(26) TF_R(6)
  x1 += b.y; x0 += a.x + x1;          // inject (k0, k1+3)
  x1 = __funnelshift_l(x1, x1, 17); x1 ^= x0;
  TF_R(29) TF_R(16) TF_R(24)
  x1 += b.z; x0 += a.y + x1;          // inject (k1, k2+4)
  x1 = __funnelshift_l(x1, x1, 13); x1 ^= x0;
  TF_R(15) TF_R(26) TF_R(6)
  return (x0 + a.z) ^ (x1 + b.w);     // final inject (k2, k0+5) + fold
#undef TF_R
}

__device__ __forceinline__ float bits_to_u01(unsigned bits) {
  return __uint_as_float((bits >> 9) | 0x3F800000u) - 1.0f;
}

// u in [-0.99999994, 0.99999988]; NEVER -1 (u01 >= 0). Matches reference rounding.
__device__ __forceinline__ float bits_to_u(unsigned bits) {
  return fmaf(bits_to_u01(bits), 2.0f, -0.99999994f);
}

// step = DT * exp(0.01*sqrt(2)*erfinv(u)), fully log2-domain, BRANCH-FREE:
// both erfinv arms evaluated, FSEL at the end.
__device__ __forceinline__ float jitter_step(float u) {
  float t1 = fmaf(u, -u, 1.0f);           // >= 1.19e-7 (u != +-1)
  float l2 = lg2f(t1);                    // = -w2  (<= 0, finite)

  // main arm (w2 < 7.2135)
  float s = -l2 - 3.6067376f;
  float pm = fmaf(3.0550e-11f, s, 5.3843e-10f);
  pm = fmaf(pm, s, -7.9726e-09f);
  pm = fmaf(pm, s, -1.43362e-08f);
  pm = fmaf(pm, s, 1.029444e-06f);
  pm = fmaf(pm, s, -8.518764e-06f);
  pm = fmaf(pm, s, -4.095214e-05f);
  pm = fmaf(pm, s, 3.488122e-03f);
  pm = fmaf(pm, s, 3.063295e-02f);

  // tail arm (w2 >= 7.2135)
  float wn = l2 * -0.69314718f;
  float v = sqrt_ap(wn) - 3.0f;
  float q = fmaf(-0.000200214257f, v, 0.000100950558f);
  q = fmaf(q, v, 0.00134934322f);
  q = fmaf(q, v, -0.00367342844f);
  q = fmaf(q, v, 0.00573950773f);
  q = fmaf(q, v, -0.0076224613f);
  q = fmaf(q, v, 0.00943887047f);
  q = fmaf(q, v, 1.00167406f);
  q = fmaf(q, v, 2.83297682f);
  float pt = q * 0.0204027886f;

  float pl = (l2 > -7.2135f) ? pm : pt;
  return ex2f(fmaf(pl, u, -5.6438562f));  // 2^(y2 + log2(0.02))
}

// ---------------- kernels ----------------
__global__ void init_kernel() {
  int i = threadIdx.x;
  if (i == 0) { g_minb = 0x7F7FFFFFu; g_maxb = 0u; }
  if (i <= NSTEPS) {
    unsigned k0, k1;
    tf_block(0u, 42u, 0u, (unsigned)i, k0, k1);      // fold_in(key(42), i)
    unsigned k2 = k0 ^ k1 ^ 0x1BD11BDAu;
    g_keys8[2 * i]     = make_uint4(k0, k1, k2, k2 + 1u);
    g_keys8[2 * i + 1] = make_uint4(k0 + 2u, k1 + 3u, k2 + 4u, k0 + 5u);
  }
}

__global__ void transpose_kernel(const float* __restrict__ tpl) {
  int i = blockIdx.x * blockDim.x + threadIdx.x;      // over B_*NVOX voxels
  if (i >= B_ * NVOX) return;
  int b = i / NVOX;
  int v = i - b * NVOX;
  const float* base = tpl + (size_t)b * 4 * NVOX + v;
  float4 o;
  o.x = base[0];
  o.y = base[NVOX];
  o.z = base[2 * NVOX];
  o.w = base[3 * NVOX];
  g_grid[i] = o;
}

__global__ __launch_bounds__(128, 6) void march_kernel(
    const float* __restrict__ rot, const float* __restrict__ cam,
    const float* __restrict__ foc, const float* __restrict__ pp,
    const float* __restrict__ pix, const float* __restrict__ bg,
    float* __restrict__ out) {
  __shared__ uint4 sk[(NSTEPS + 1) * 2];
  for (int i = threadIdx.y * 32 + threadIdx.x; i < (NSTEPS + 1) * 2; i += 128)
    sk[i] = g_keys8[i];
  __syncthreads();

  int x = blockIdx.x * 32 + threadIdx.x;
  int y = blockIdx.y * 4 + threadIdx.y;
  int b = blockIdx.z;
  int p = (b * H_ + y) * W_ + x;

  // ray direction
  float px = pix[(size_t)p * 2 + 0];
  float py = pix[(size_t)p * 2 + 1];
  float vx = (px - pp[b * 2 + 0]) / foc[b * 2 + 0];
  float vy = (py - pp[b * 2 + 1]) / foc[b * 2 + 1];
  const float* R = rot + b * 9;
  float rdx = R[0] * vx + R[3] * vy + R[6];
  float rdy = R[1] * vx + R[4] * vy + R[7];
  float rdz = R[2] * vx + R[5] * vy + R[8];
  float nrm = sqrtf(rdx * rdx + rdy * rdy + rdz * rdz);
  rdx /= nrm; rdy /= nrm; rdz /= nrm;

  float cx = cam[b * 3 + 0], cy = cam[b * 3 + 1], cz = cam[b * 3 + 2];

  // box intersection [-1,1]^3
  float t1x = (-1.0f - cx) / rdx, t2x = (1.0f - cx) / rdx;
  float t1y = (-1.0f - cy) / rdy, t2y = (1.0f - cy) / rdy;
  float t1z = (-1.0f - cz) / rdz, t2z = (1.0f - cz) / rdz;
  float tmin = fmaxf(fminf(t1x, t2x), fmaxf(fminf(t1y, t2y), fminf(t1z, t2z)));
  float tmax = fminf(fmaxf(t1x, t2x), fminf(fmaxf(t1y, t2y), fmaxf(t1z, t2z)));
  bool hit = tmin < tmax;
  float t = fmaxf(hit ? tmin : 0.0f, 0.0f);
  float t_exit = hit ? (tmax + 0.04f) : -1e30f;  // conservative: t>t_exit => pos invalid

  // initial jitter: t -= DT * uniform(fold_in(key,0))
  t = t - 0.02f * bits_to_u01(rbits8(sk[0], sk[1], (unsigned)p));

  // march in grid coordinates: g = (pos + 1) * 63.5, valid <=> g in (0, 127)
  float gx = (cx + rdx * t + 1.0f) * 63.5f;
  float gy = (cy + rdy * t + 1.0f) * 63.5f;
  float gz = (cz + rdz * t + 1.0f) * 63.5f;
  float rgx = rdx * 63.5f, rgy = rdy * 63.5f, rgz = rdz * 63.5f;

  float rr = 0.f, rg = 0.f, rb = 0.f, ra = 0.f, rl = 0.f;
  const float4* __restrict__ grid = g_grid + (size_t)b * NVOX;
  const uint4* kp = sk + 2;  // keys for step 0

  int i = 0;
#pragma unroll 1
  for (; i < NSTEPS; ) {
    uint4 ka = kp[0], kb = kp[1];
    kp += 2;
    float u = bits_to_u(rbits8(ka, kb, (unsigned)p));
    float step = jitter_step(u);

    bool active = (ra < 1.0f) &
                  (gx > 0.0f) & (gx < 127.0f) &
                  (gy > 0.0f) & (gy < 127.0f) &
                  (gz > 0.0f) & (gz < 127.0f);

    // Branch-free sampling: clamp indices to safe range, always load, select at end.
    int ix = min(__float2int_rz(fmaxf(gx, 0.0f)), 126);
    int iy = min(__float2int_rz(fmaxf(gy, 0.0f)), 126);
    int iz = min(__float2int_rz(fmaxf(gz, 0.0f)), 126);
    float wx = gx - (float)ix, wy = gy - (float)iy, wz = gz - (float)iz;
    float ox = 1.0f - wx, oy = 1.0f - wy, oz = 1.0f - wz;
    float w00 = ox * oy, w10 = wx * oy, w01 = ox * wy, w11 = wx * wy;
    float v000 = w00 * oz, v100 = w10 * oz, v010 = w01 * oz, v110 = w11 * oz;
    float v001 = w00 * wz, v101 = w10 * wz, v011 = w01 * wz, v111 = w11 * wz;

    const float4* base = grid + ((iz * D_ + iy) * D_ + ix);
    float4 a000 = __ldg(base);
    float4 a100 = __ldg(base + 1);
    float4 a010 = __ldg(base + D_);
    float4 a110 = __ldg(base + D_ + 1);
    float4 a001 = __ldg(base + D_ * D_);
    float4 a101 = __ldg(base + D_ * D_ + 1);
    float4 a011 = __ldg(base + D_ * D_ + D_);
    float4 a111 = __ldg(base + D_ * D_ + D_ + 1);

    float sxr = v000 * a000.x, sxg = v000 * a000.y, sxb = v000 * a000.z, sxa = v000 * a000.w;
    sxr = fmaf(v100, a100.x, sxr); sxg = fmaf(v100, a100.y, sxg);
    sxb = fmaf(v100, a100.z, sxb); sxa = fmaf(v100, a100.w, sxa);
    sxr = fmaf(v010, a010.x, sxr); sxg = fmaf(v010, a010.y, sxg);
    sxb = fmaf(v010, a010.z, sxb); sxa = fmaf(v010, a010.w, sxa);
    sxr = fmaf(v110, a110.x, sxr); sxg = fmaf(v110, a110.y, sxg);
    sxb = fmaf(v110, a110.z, sxb); sxa = fmaf(v110, a110.w, sxa);
    sxr = fmaf(v001, a001.x, sxr); sxg = fmaf(v001, a001.y, sxg);
    sxb = fmaf(v001, a001.z, sxb); sxa = fmaf(v001, a001.w, sxa);
    sxr = fmaf(v101, a101.x, sxr); sxg = fmaf(v101, a101.y, sxg);
    sxb = fmaf(v101, a101.z, sxb); sxa = fmaf(v101, a101.w, sxa);
    sxr = fmaf(v011, a011.x, sxr); sxg = fmaf(v011, a011.y, sxg);
    sxb = fmaf(v011, a011.z, sxb); sxa = fmaf(v011, a011.w, sxa);
    sxr = fmaf(v111, a111.x, sxr); sxg = fmaf(v111, a111.y, sxg);
    sxb = fmaf(v111, a111.z, sxb); sxa = fmaf(v111, a111.w, sxa);

    float cand = fminf(fmaf(sxa, step, ra), 1.0f) - ra;
    float contrib = active ? cand : 0.0f;
    rr = fmaf(sxr, contrib, rr);
    rg = fmaf(sxg, contrib, rg);
    rb = fmaf(sxb, contrib, rb);
    ra += contrib;
    rl += (contrib == 0.0f) ? step : 0.0f;

    gx = fmaf(rgx, step, gx);
    gy = fmaf(rgy, step, gy);
    gz = fmaf(rgz, step, gz);
    t += step;
    i++;

    // terminal: past box exit (convex, never re-enters) or alpha saturated exactly.
    if (__all_sync(0xFFFFFFFFu, (t > t_exit) | (ra >= 1.0f))) break;
  }

  // tail: contrib is identically 0; only ray_length accumulates (2 interleaved chains).
#pragma unroll 1
  for (; i + 2 <= NSTEPS; i += 2) {
    uint4 ka0 = kp[0], kb0 = kp[1], ka1 = kp[2], kb1 = kp[3];
    kp += 4;
    float s0 = jitter_step(bits_to_u(rbits8(ka0, kb0, (unsigned)p)));
    float s1 = jitter_step(bits_to_u(rbits8(ka1, kb1, (unsigned)p)));
    rl += s0;
    rl += s1;
  }
  if (i < NSTEPS)
    rl += jitter_step(bits_to_u(rbits8(kp[0], kp[1], (unsigned)p)));

  // compositing with background
  float b0 = fmaxf(bg[((size_t)(b * 3 + 0) * H_ + y) * W_ + x], 0.0f);
  float b1 = fmaxf(bg[((size_t)(b * 3 + 1) * H_ + y) * W_ + x], 0.0f);
  float b2 = fmaxf(bg[((size_t)(b * 3 + 2) * H_ + y) * W_ + x], 0.0f);
  float om = 1.0f - ra;
  out[((size_t)(b * 3 + 0) * H_ + y) * W_ + x] = rr + om * b0;
  out[((size_t)(b * 3 + 1) * H_ + y) * W_ + x] = rg + om * b1;
  out[((size_t)(b * 3 + 2) * H_ + y) * W_ + x] = rb + om * b2;
  out[A_OFF + p] = ra;
  out[L_OFF + p] = rl;  // raw; normalized by finalize_kernel

  // block min/max reduction of rl (>= 0, so uint order == float order)
  unsigned lb = __float_as_uint(rl);
  unsigned mn = lb, mx = lb;
#pragma unroll
  for (int o = 16; o; o >>= 1) {
    mn = min(mn, __shfl_xor_sync(0xFFFFFFFFu, mn, o));
    mx = max(mx, __shfl_xor_sync(0xFFFFFFFFu, mx, o));
  }
  __shared__ unsigned smn[4], smx[4];
  if (threadIdx.x == 0) { smn[threadIdx.y] = mn; smx[threadIdx.y] = mx; }
  __syncthreads();
  if (threadIdx.x == 0 && threadIdx.y == 0) {
    mn = min(min(smn[0], smn[1]), min(smn[2], smn[3]));
    mx = max(max(smx[0], smx[1]), max(smx[2], smx[3]));
    atomicMin(&g_minb, mn);
    atomicMax(&g_maxb, mx);
  }
}

__global__ void finalize_kernel(float* __restrict__ out) {
  int p = blockIdx.x * blockDim.x + threadIdx.x;
  if (p >= NPIX) return;
  float denom = __uint_as_float(g_maxb) + __uint_as_float(g_minb);
  out[L_OFF + p] = out[A_OFF + p] * out[L_OFF + p] / denom;
}

// ---------------- launch ----------------
extern "C" void kernel_launch(void* const* d_in, const int* in_sizes, int n_in,
                              void* d_out, int out_size) {
  const float* rot = (const float*)d_in[0];  // camera_rotation (B,3,3)
  const float* cam = (const float*)d_in[1];  // camera_position (B,3)
  const float* foc = (const float*)d_in[2];  // focal (B,2)
  const float* pp  = (const float*)d_in[3];  // principal_point (B,2)
  const float* pix = (const float*)d_in[4];  // pixel_coords (B,H,W,2)
  const float* tpl = (const float*)d_in[5];  // template (B,4,D,D,D)
  const float* bg  = (const float*)d_in[6];  // background (B,3,H,W)
  float* out = (float*)d_out;

  init_kernel<<<1, 256>>>();
  transpose_kernel<<<(B_ * NVOX + 255) / 256, 256>>>(tpl);
  dim3 blk(32, 4, 1);
  dim3 grd(W_ / 32, H_ / 4, B_);
  march_kernel<<<grd, blk>>>(rot, cam, foc, pp, pix, bg, out);
  finalize_kernel<<<(NPIX + 255) / 256, 256>>>(out);
}

// round 7
// speedup vs baseline: 1.1011x; 1.1011x over previous
#include <cuda_runtime.h>
#include <math.h>

// Problem constants (match reference)
#define B_ 2
#define H_ 512
#define W_ 512
#define D_ 128
#define NSTEPS 180
#define NPIX (B_ * H_ * W_)
#define NVOX (D_ * D_ * D_)

// Output packing: [rgb (B,3,H,W)][alpha (B,1,H,W)][length (B,1,H,W)]
#define A_OFF (B_ * 3 * H_ * W_)
#define L_OFF (A_OFF + NPIX)

// ---------------- device scratch (static allocations only) ----------------
__device__ float4 g_grid[(size_t)B_ * NVOX];     // AoS repacked template (~67MB, L2-resident)
__device__ uint4 g_keys8[(NSTEPS + 1) * 2];      // per-step folded threefry key schedule
__device__ unsigned g_minb, g_maxb;              // global min/max of raw ray_length (uint-punned)

__device__ __forceinline__ float ex2f(float x) {
  float r;
  asm("ex2.approx.f32 %0, %1;" : "=f"(r) : "f"(x));
  return r;
}
__device__ __forceinline__ float lg2f(float x) {
  float r;
  asm("lg2.approx.f32 %0, %1;" : "=f"(r) : "f"(x));
  return r;
}

// ---------------- threefry2x32 (reference block, host-side key schedule) ----------------
__device__ __forceinline__ void tf_block(unsigned k0, unsigned k1, unsigned x0, unsigned x1,
                                         unsigned& o0, unsigned& o1) {
  unsigned k2 = k0 ^ k1 ^ 0x1BD11BDAu;
#define TF_R(r) { x0 += x1; x1 = (x1 << (r)) | (x1 >> (32 - (r))); x1 ^= x0; }
  x0 += k0; x1 += k1;
  TF_R(13) TF_R(15) TF_R(26) TF_R(6)
  x0 += k1; x1 += k2 + 1u;
  TF_R(17) TF_R(29) TF_R(16) TF_R(24)
  x0 += k2; x1 += k0 + 2u;
  TF_R(13) TF_R(15) TF_R(26) TF_R(6)
  x0 += k0; x1 += k1 + 3u;
  TF_R(17) TF_R(29) TF_R(16) TF_R(24)
  x0 += k1; x1 += k2 + 4u;
  TF_R(13) TF_R(15) TF_R(26) TF_R(6)
  x0 += k2; x1 += k0 + 5u;
#undef TF_R
  o0 = x0; o1 = x1;
}

// threefry with precomputed key schedule: a = {k0,k1,k2,k2+1}, b = {k0+2,k1+3,k2+4,k0+5}
// counter = (hi=0, lo=p); returns o0 ^ o1 (partitionable fold). Key injections fused
// into the following round's add (3-input IADD3).
__device__ __forceinline__ unsigned rbits8(uint4 a, uint4 b, unsigned p) {
#define TF_R(r)  { x0 += x1; x1 = __funnelshift_l(x1, x1, (r)); x1 ^= x0; }
  unsigned x1 = p + a.y;              // p + k1
  unsigned x0 = a.x + x1;             // (0 + k0) + x1  [round 1 add]
  x1 = __funnelshift_l(x1, x1, 13); x1 ^= x0;
  TF_R(15) TF_R(26) TF_R(6)
  x1 += a.w; x0 += a.y + x1;          // inject (k1, k2+1) fused with round add
  x1 = __funnelshift_l(x1, x1, 17); x1 ^= x0;
  TF_R(29) TF_R(16) TF_R(24)
  x1 += b.x; x0 += a.z + x1;          // inject (k2, k0+2)
  x1 = __funnelshift_l(x1, x1, 13); x1 ^= x0;
  TF_R(15) TF_R(26) TF_R(6)
  x1 += b.y; x0 += a.x + x1;          // inject (k0, k1+3)
  x1 = __funnelshift_l(x1, x1, 17); x1 ^= x0;
  TF_R(29) TF_R(16) TF_R(24)
  x1 += b.z; x0 += a.y + x1;          // inject (k1, k2+4)
  x1 = __funnelshift_l(x1, x1, 13); x1 ^= x0;
  TF_R(15) TF_R(26) TF_R(6)
  return (x0 + a.z) ^ (x1 + b.w);     // final inject (k2, k0+5) + fold
#undef TF_R
}

__device__ __forceinline__ float bits_to_u01(unsigned bits) {
  return __uint_as_float((bits >> 9) | 0x3F800000u) - 1.0f;
}

// u in [-0.99999994, 0.99999988]; never -1 (u01 >= 0). Matches reference rounding.
__device__ __forceinline__ float bits_to_u(unsigned bits) {
  return fmaf(bits_to_u01(bits), 2.0f, -0.99999994f);
}

// Full-accuracy jitter (main loop): branchy two-arm Giles erfinv, log2 domain.
__device__ __forceinline__ float jitter_step(float u) {
  float t1 = fmaf(u, -u, 1.0f);
  float l2 = lg2f(t1);                    // = -w2
  float pl;
  if (l2 > -7.2135f) {                    // common branch (w < 5 natural)
    float s = -l2 - 3.6067376f;
    pl = fmaf(3.0550e-11f, s, 5.3843e-10f);
    pl = fmaf(pl, s, -7.9726e-09f);
    pl = fmaf(pl, s, -1.43362e-08f);
    pl = fmaf(pl, s, 1.029444e-06f);
    pl = fmaf(pl, s, -8.518764e-06f);
    pl = fmaf(pl, s, -4.095214e-05f);
    pl = fmaf(pl, s, 3.488122e-03f);
    pl = fmaf(pl, s, 3.063295e-02f);
  } else {                                // rare tail (|u| > 0.99664)
    float wn = l2 * -0.69314718f;
    float v = sqrtf(wn) - 3.0f;
    float q = fmaf(-0.000200214257f, v, 0.000100950558f);
    q = fmaf(q, v, 0.00134934322f);
    q = fmaf(q, v, -0.00367342844f);
    q = fmaf(q, v, 0.00573950773f);
    q = fmaf(q, v, -0.0076224613f);
    q = fmaf(q, v, 0.00943887047f);
    q = fmaf(q, v, 1.00167406f);
    q = fmaf(q, v, 2.83297682f);
    pl = q * 0.0204027886f;
  }
  return ex2f(fmaf(pl, u, -5.6438562f));  // 2^(y2 + log2(0.02))
}

// Cheap jitter (tail only; feeds ray_length, no position feedback):
// single central arm with s clamped to its domain. Error <= 0.7% on 0.34% of draws.
__device__ __forceinline__ float jitter_step_tail(float u) {
  float t1 = fmaf(u, -u, 1.0f);
  float l2 = lg2f(t1);
  float s = fminf(-l2 - 3.6067376f, 3.6068f);
  float pm = fmaf(3.0550e-11f, s, 5.3843e-10f);
  pm = fmaf(pm, s, -7.9726e-09f);
  pm = fmaf(pm, s, -1.43362e-08f);
  pm = fmaf(pm, s, 1.029444e-06f);
  pm = fmaf(pm, s, -8.518764e-06f);
  pm = fmaf(pm, s, -4.095214e-05f);
  pm = fmaf(pm, s, 3.488122e-03f);
  pm = fmaf(pm, s, 3.063295e-02f);
  return ex2f(fmaf(pm, u, -5.6438562f));
}

// RNG + full jitter for step index via key pointer
__device__ __forceinline__ float step_for(const uint4* kp, unsigned p) {
  return jitter_step(bits_to_u(rbits8(kp[0], kp[1], p)));
}

// ---------------- kernels ----------------
__global__ void init_kernel() {
  int i = threadIdx.x;
  if (i == 0) { g_minb = 0x7F7FFFFFu; g_maxb = 0u; }
  if (i <= NSTEPS) {
    unsigned k0, k1;
    tf_block(0u, 42u, 0u, (unsigned)i, k0, k1);      // fold_in(key(42), i)
    unsigned k2 = k0 ^ k1 ^ 0x1BD11BDAu;
    g_keys8[2 * i]     = make_uint4(k0, k1, k2, k2 + 1u);
    g_keys8[2 * i + 1] = make_uint4(k0 + 2u, k1 + 3u, k2 + 4u, k0 + 5u);
  }
}

__global__ void transpose_kernel(const float* __restrict__ tpl) {
  int i = blockIdx.x * blockDim.x + threadIdx.x;      // over B_*NVOX voxels
  if (i >= B_ * NVOX) return;
  int b = i / NVOX;
  int v = i - b * NVOX;
  const float* base = tpl + (size_t)b * 4 * NVOX + v;
  float4 o;
  o.x = base[0];
  o.y = base[NVOX];
  o.z = base[2 * NVOX];
  o.w = base[3 * NVOX];
  g_grid[i] = o;
}

__global__ __launch_bounds__(128, 6) void march_kernel(
    const float* __restrict__ rot, const float* __restrict__ cam,
    const float* __restrict__ foc, const float* __restrict__ pp,
    const float* __restrict__ pix, const float* __restrict__ bg,
    float* __restrict__ out) {
  __shared__ uint4 sk[(NSTEPS + 1) * 2];
  for (int i = threadIdx.y * 32 + threadIdx.x; i < (NSTEPS + 1) * 2; i += 128)
    sk[i] = g_keys8[i];
  __syncthreads();

  int x = blockIdx.x * 32 + threadIdx.x;
  int y = blockIdx.y * 4 + threadIdx.y;
  int b = blockIdx.z;
  int p = (b * H_ + y) * W_ + x;

  // ray direction
  float px = pix[(size_t)p * 2 + 0];
  float py = pix[(size_t)p * 2 + 1];
  float vx = (px - pp[b * 2 + 0]) / foc[b * 2 + 0];
  float vy = (py - pp[b * 2 + 1]) / foc[b * 2 + 1];
  const float* R = rot + b * 9;
  float rdx = R[0] * vx + R[3] * vy + R[6];
  float rdy = R[1] * vx + R[4] * vy + R[7];
  float rdz = R[2] * vx + R[5] * vy + R[8];
  float nrm = sqrtf(rdx * rdx + rdy * rdy + rdz * rdz);
  rdx /= nrm; rdy /= nrm; rdz /= nrm;

  float cx = cam[b * 3 + 0], cy = cam[b * 3 + 1], cz = cam[b * 3 + 2];

  // box intersection [-1,1]^3
  float t1x = (-1.0f - cx) / rdx, t2x = (1.0f - cx) / rdx;
  float t1y = (-1.0f - cy) / rdy, t2y = (1.0f - cy) / rdy;
  float t1z = (-1.0f - cz) / rdz, t2z = (1.0f - cz) / rdz;
  float tmin = fmaxf(fminf(t1x, t2x), fmaxf(fminf(t1y, t2y), fminf(t1z, t2z)));
  float tmax = fminf(fmaxf(t1x, t2x), fminf(fmaxf(t1y, t2y), fmaxf(t1z, t2z)));
  bool hit = tmin < tmax;
  float t = fmaxf(hit ? tmin : 0.0f, 0.0f);
  float t_exit = hit ? (tmax + 0.04f) : -1e30f;  // conservative: t>t_exit => pos invalid

  // initial jitter: t -= DT * uniform(fold_in(key,0))
  t = t - 0.02f * bits_to_u01(rbits8(sk[0], sk[1], (unsigned)p));

  // march in grid coordinates: g = (pos + 1) * 63.5, valid <=> g in (0, 127)
  float gx = (cx + rdx * t + 1.0f) * 63.5f;
  float gy = (cy + rdy * t + 1.0f) * 63.5f;
  float gz = (cz + rdz * t + 1.0f) * 63.5f;
  float rgx = rdx * 63.5f, rgy = rdy * 63.5f, rgz = rdz * 63.5f;

  float rr = 0.f, rg = 0.f, rb = 0.f, ra = 0.f, rl = 0.f;
  const float4* __restrict__ grid = g_grid + (size_t)b * NVOX;
  const uint4* kp = sk + 2;  // keys for step 0

  int i = 0;
#pragma unroll 2
  for (; i < NSTEPS; ) {
    float step = step_for(kp, (unsigned)p);
    kp += 2;

    bool active = (ra < 1.0f) &
                  (gx > 0.0f) & (gx < 127.0f) &
                  (gy > 0.0f) & (gy < 127.0f) &
                  (gz > 0.0f) & (gz < 127.0f);

    float contrib = 0.0f;
    if (active) {
      int ix = (int)gx, iy = (int)gy, iz = (int)gz;  // trunc == floor (g > 0)
      float wx = gx - (float)ix, wy = gy - (float)iy, wz = gz - (float)iz;
      float ox = 1.0f - wx, oy = 1.0f - wy, oz = 1.0f - wz;
      float w00 = ox * oy, w10 = wx * oy, w01 = ox * wy, w11 = wx * wy;
      float v000 = w00 * oz, v100 = w10 * oz, v010 = w01 * oz, v110 = w11 * oz;
      float v001 = w00 * wz, v101 = w10 * wz, v011 = w01 * wz, v111 = w11 * wz;

      const float4* base = grid + ((iz * D_ + iy) * D_ + ix);
      float4 a000 = __ldg(base);
      float4 a100 = __ldg(base + 1);
      float4 a010 = __ldg(base + D_);
      float4 a110 = __ldg(base + D_ + 1);
      float4 a001 = __ldg(base + D_ * D_);
      float4 a101 = __ldg(base + D_ * D_ + 1);
      float4 a011 = __ldg(base + D_ * D_ + D_);
      float4 a111 = __ldg(base + D_ * D_ + D_ + 1);

      float sxr = v000 * a000.x, sxg = v000 * a000.y, sxb = v000 * a000.z, sxa = v000 * a000.w;
      sxr = fmaf(v100, a100.x, sxr); sxg = fmaf(v100, a100.y, sxg);
      sxb = fmaf(v100, a100.z, sxb); sxa = fmaf(v100, a100.w, sxa);
      sxr = fmaf(v010, a010.x, sxr); sxg = fmaf(v010, a010.y, sxg);
      sxb = fmaf(v010, a010.z, sxb); sxa = fmaf(v010, a010.w, sxa);
      sxr = fmaf(v110, a110.x, sxr); sxg = fmaf(v110, a110.y, sxg);
      sxb = fmaf(v110, a110.z, sxb); sxa = fmaf(v110, a110.w, sxa);
      sxr = fmaf(v001, a001.x, sxr); sxg = fmaf(v001, a001.y, sxg);
      sxb = fmaf(v001, a001.z, sxb); sxa = fmaf(v001, a001.w, sxa);
      sxr = fmaf(v101, a101.x, sxr); sxg = fmaf(v101, a101.y, sxg);
      sxb = fmaf(v101, a101.z, sxb); sxa = fmaf(v101, a101.w, sxa);
      sxr = fmaf(v011, a011.x, sxr); sxg = fmaf(v011, a011.y, sxg);
      sxb = fmaf(v011, a011.z, sxb); sxa = fmaf(v011, a011.w, sxa);
      sxr = fmaf(v111, a111.x, sxr); sxg = fmaf(v111, a111.y, sxg);
      sxb = fmaf(v111, a111.z, sxb); sxa = fmaf(v111, a111.w, sxa);

      contrib = fminf(fmaf(sxa, step, ra), 1.0f) - ra;
      rr = fmaf(sxr, contrib, rr);
      rg = fmaf(sxg, contrib, rg);
      rb = fmaf(sxb, contrib, rb);
      ra += contrib;
    }
    if (contrib == 0.0f) rl += step;

    gx = fmaf(rgx, step, gx);
    gy = fmaf(rgy, step, gy);
    gz = fmaf(rgz, step, gz);
    t += step;
    i++;

    // terminal: past box exit (convex, never re-enters) or alpha saturated exactly.
    if (__all_sync(0xFFFFFFFFu, (t > t_exit) | (ra >= 1.0f))) break;
  }

  // tail: contrib identically 0; only ray_length accumulates.
  // Cheap single-arm jitter + two accumulators (independent chains).
  float rl0 = 0.0f, rl1 = 0.0f;
#pragma unroll 1
  for (; i + 2 <= NSTEPS; i += 2) {
    uint4 ka0 = kp[0], kb0 = kp[1], ka1 = kp[2], kb1 = kp[3];
    kp += 4;
    rl0 += jitter_step_tail(bits_to_u(rbits8(ka0, kb0, (unsigned)p)));
    rl1 += jitter_step_tail(bits_to_u(rbits8(ka1, kb1, (unsigned)p)));
  }
  if (i < NSTEPS)
    rl0 += jitter_step_tail(bits_to_u(rbits8(kp[0], kp[1], (unsigned)p)));
  rl += rl0 + rl1;

  // compositing with background
  float b0 = fmaxf(bg[((size_t)(b * 3 + 0) * H_ + y) * W_ + x], 0.0f);
  float b1 = fmaxf(bg[((size_t)(b * 3 + 1) * H_ + y) * W_ + x], 0.0f);
  float b2 = fmaxf(bg[((size_t)(b * 3 + 2) * H_ + y) * W_ + x], 0.0f);
  float om = 1.0f - ra;
  out[((size_t)(b * 3 + 0) * H_ + y) * W_ + x] = rr + om * b0;
  out[((size_t)(b * 3 + 1) * H_ + y) * W_ + x] = rg + om * b1;
  out[((size_t)(b * 3 + 2) * H_ + y) * W_ + x] = rb + om * b2;
  out[A_OFF + p] = ra;
  out[L_OFF + p] = rl;  // raw; normalized by finalize_kernel

  // block min/max reduction of rl (>= 0, so uint order == float order)
  unsigned lb = __float_as_uint(rl);
  unsigned mn = lb, mx = lb;
#pragma unroll
  for (int o = 16; o; o >>= 1) {
    mn = min(mn, __shfl_xor_sync(0xFFFFFFFFu, mn, o));
    mx = max(mx, __shfl_xor_sync(0xFFFFFFFFu, mx, o));
  }
  __shared__ unsigned smn[4], smx[4];
  if (threadIdx.x == 0) { smn[threadIdx.y] = mn; smx[threadIdx.y] = mx; }
  __syncthreads();
  if (threadIdx.x == 0 && threadIdx.y == 0) {
    mn = min(min(smn[0], smn[1]), min(smn[2], smn[3]));
    mx = max(max(smx[0], smx[1]), max(smx[2], smx[3]));
    atomicMin(&g_minb, mn);
    atomicMax(&g_maxb, mx);
  }
}

__global__ void finalize_kernel(float* __restrict__ out) {
  int p = blockIdx.x * blockDim.x + threadIdx.x;
  if (p >= NPIX) return;
  float denom = __uint_as_float(g_maxb) + __uint_as_float(g_minb);
  out[L_OFF + p] = out[A_OFF + p] * out[L_OFF + p] / denom;
}

// ---------------- launch ----------------
extern "C" void kernel_launch(void* const* d_in, const int* in_sizes, int n_in,
                              void* d_out, int out_size) {
  const float* rot = (const float*)d_in[0];  // camera_rotation (B,3,3)
  const float* cam = (const float*)d_in[1];  // camera_position (B,3)
  const float* foc = (const float*)d_in[2];  // focal (B,2)
  const float* pp  = (const float*)d_in[3];  // principal_point (B,2)
  const float* pix = (const float*)d_in[4];  // pixel_coords (B,H,W,2)
  const float* tpl = (const float*)d_in[5];  // template (B,4,D,D,D)
  const float* bg  = (const float*)d_in[6];  // background (B,3,H,W)
  float* out = (float*)d_out;

  init_kernel<<<1, 256>>>();
  transpose_kernel<<<(B_ * NVOX + 255) / 256, 256>>>(tpl);
  dim3 blk(32, 4, 1);
  dim3 grd(W_ / 32, H_ / 4, B_);
  march_kernel<<<grd, blk>>>(rot, cam, foc, pp, pix, bg, out);
  finalize_kernel<<<(NPIX + 255) / 256, 256>>>(out);
}

// round 8
// speedup vs baseline: 1.1761x; 1.0682x over previous
#include <cuda_runtime.h>
#include <math.h>

// Problem constants (match reference)
#define B_ 2
#define H_ 512
#define W_ 512
#define D_ 128
#define NSTEPS 180
#define NPIX (B_ * H_ * W_)
#define NVOX (D_ * D_ * D_)

// Output packing: [rgb (B,3,H,W)][alpha (B,1,H,W)][length (B,1,H,W)]
#define A_OFF (B_ * 3 * H_ * W_)
#define L_OFF (A_OFF + NPIX)

// ---------------- device scratch (static allocations only) ----------------
__device__ float4 g_grid[(size_t)B_ * NVOX];     // AoS repacked template (~67MB, L2-resident)
__device__ uint4 g_keys8[(NSTEPS + 1) * 2];      // per-step folded threefry key schedule
__device__ unsigned g_minb, g_maxb;              // global min/max of raw ray_length (uint-punned)

__device__ __forceinline__ float ex2f(float x) {
  float r;
  asm("ex2.approx.f32 %0, %1;" : "=f"(r) : "f"(x));
  return r;
}
__device__ __forceinline__ float lg2f(float x) {
  float r;
  asm("lg2.approx.f32 %0, %1;" : "=f"(r) : "f"(x));
  return r;
}

// ---------------- threefry2x32 (reference block, host-side key schedule) ----------------
__device__ __forceinline__ void tf_block(unsigned k0, unsigned k1, unsigned x0, unsigned x1,
                                         unsigned& o0, unsigned& o1) {
  unsigned k2 = k0 ^ k1 ^ 0x1BD11BDAu;
#define TF_R(r) { x0 += x1; x1 = (x1 << (r)) | (x1 >> (32 - (r))); x1 ^= x0; }
  x0 += k0; x1 += k1;
  TF_R(13) TF_R(15) TF_R(26) TF_R(6)
  x0 += k1; x1 += k2 + 1u;
  TF_R(17) TF_R(29) TF_R(16) TF_R(24)
  x0 += k2; x1 += k0 + 2u;
  TF_R(13) TF_R(15) TF_R(26) TF_R(6)
  x0 += k0; x1 += k1 + 3u;
  TF_R(17) TF_R(29) TF_R(16) TF_R(24)
  x0 += k1; x1 += k2 + 4u;
  TF_R(13) TF_R(15) TF_R(26) TF_R(6)
  x0 += k2; x1 += k0 + 5u;
#undef TF_R
  o0 = x0; o1 = x1;
}

// threefry with precomputed key schedule: a = {k0,k1,k2,k2+1}, b = {k0+2,k1+3,k2+4,k0+5}
// counter = (hi=0, lo=p); returns o0 ^ o1 (partitionable fold). Key injections fused
// into the following round's add (3-input IADD3).
__device__ __forceinline__ unsigned rbits8(uint4 a, uint4 b, unsigned p) {
#define TF_R(r)  { x0 += x1; x1 = __funnelshift_l(x1, x1, (r)); x1 ^= x0; }
  unsigned x1 = p + a.y;              // p + k1
  unsigned x0 = a.x + x1;             // (0 + k0) + x1  [round 1 add]
  x1 = __funnelshift_l(x1, x1, 13); x1 ^= x0;
  TF_R(15) TF_R(26) TF_R(6)
  x1 += a.w; x0 += a.y + x1;          // inject (k1, k2+1) fused with round add
  x1 = __funnelshift_l(x1, x1, 17); x1 ^= x0;
  TF_R(29) TF_R(16) TF_R(24)
  x1 += b.x; x0 += a.z + x1;          // inject (k2, k0+2)
  x1 = __funnelshift_l(x1, x1, 13); x1 ^= x0;
  TF_R(15) TF_R(26) TF_R(6)
  x1 += b.y; x0 += a.x + x1;          // inject (k0, k1+3)
  x1 = __funnelshift_l(x1, x1, 17); x1 ^= x0;
  TF_R(29) TF_R(16) TF_R(24)
  x1 += b.z; x0 += a.y + x1;          // inject (k1, k2+4)
  x1 = __funnelshift_l(x1, x1, 13); x1 ^= x0;
  TF_R(15) TF_R(26) TF_R(6)
  return (x0 + a.z) ^ (x1 + b.w);     // final inject (k2, k0+5) + fold
#undef TF_R
}

__device__ __forceinline__ float bits_to_u01(unsigned bits) {
  return __uint_as_float((bits >> 9) | 0x3F800000u) - 1.0f;
}

// u in [-0.99999994, 0.99999988]; never -1 (u01 >= 0). Matches reference rounding.
__device__ __forceinline__ float bits_to_u(unsigned bits) {
  return fmaf(bits_to_u01(bits), 2.0f, -0.99999994f);
}

// Degree-4 central-arm poly for pl(s) (log2-rescaled Giles erfinv, premultiplied by
// 0.01*sqrt(2)*log2e). Dropping the degree 5-8 terms costs <= 2.2e-5 absolute on pl
// (step rel error <= 1.5e-5).
__device__ __forceinline__ float poly_central(float s) {
  float pm = fmaf(1.029444e-06f, s, -8.518764e-06f);
  pm = fmaf(pm, s, -4.095214e-05f);
  pm = fmaf(pm, s, 3.488122e-03f);
  pm = fmaf(pm, s, 3.063295e-02f);
  return pm;
}

// Full-accuracy jitter (main loop): branchy two-arm, log2 domain.
__device__ __forceinline__ float jitter_step(float u) {
  float t1 = fmaf(u, -u, 1.0f);
  float l2 = lg2f(t1);                    // = -w2
  float pl;
  if (l2 > -7.2135f) {                    // common branch
    pl = poly_central(-l2 - 3.6067376f);
  } else {                                // rare tail (|u| > 0.99664)
    float wn = l2 * -0.69314718f;
    float v = sqrtf(wn) - 3.0f;
    float q = fmaf(-0.000200214257f, v, 0.000100950558f);
    q = fmaf(q, v, 0.00134934322f);
    q = fmaf(q, v, -0.00367342844f);
    q = fmaf(q, v, 0.00573950773f);
    q = fmaf(q, v, -0.0076224613f);
    q = fmaf(q, v, 0.00943887047f);
    q = fmaf(q, v, 1.00167406f);
    q = fmaf(q, v, 2.83297682f);
    pl = q * 0.0204027886f;
  }
  return ex2f(fmaf(pl, u, -5.6438562f));  // 2^(y2 + log2(0.02))
}

// Cheap jitter (tail only; feeds ray_length, no position feedback):
// central arm with s clamped to its domain. Error <= 0.7% on 0.34% of draws.
__device__ __forceinline__ float jitter_step_tail(float u) {
  float t1 = fmaf(u, -u, 1.0f);
  float l2 = lg2f(t1);
  float s = fminf(-l2 - 3.6067376f, 3.6068f);
  return ex2f(fmaf(poly_central(s), u, -5.6438562f));
}

// RNG + full jitter for step index via key pointer
__device__ __forceinline__ float step_for(const uint4* kp, unsigned p) {
  return jitter_step(bits_to_u(rbits8(kp[0], kp[1], p)));
}

// ---------------- kernels ----------------
__global__ void init_kernel() {
  int i = threadIdx.x;
  if (i == 0) { g_minb = 0x7F7FFFFFu; g_maxb = 0u; }
  if (i <= NSTEPS) {
    unsigned k0, k1;
    tf_block(0u, 42u, 0u, (unsigned)i, k0, k1);      // fold_in(key(42), i)
    unsigned k2 = k0 ^ k1 ^ 0x1BD11BDAu;
    g_keys8[2 * i]     = make_uint4(k0, k1, k2, k2 + 1u);
    g_keys8[2 * i + 1] = make_uint4(k0 + 2u, k1 + 3u, k2 + 4u, k0 + 5u);
  }
}

__global__ void transpose_kernel(const float* __restrict__ tpl) {
  int i = blockIdx.x * blockDim.x + threadIdx.x;      // over B_*NVOX voxels
  if (i >= B_ * NVOX) return;
  int b = i / NVOX;
  int v = i - b * NVOX;
  const float* base = tpl + (size_t)b * 4 * NVOX + v;
  float4 o;
  o.x = base[0];
  o.y = base[NVOX];
  o.z = base[2 * NVOX];
  o.w = base[3 * NVOX];
  g_grid[i] = o;
}

__global__ __launch_bounds__(128, 6) void march_kernel(
    const float* __restrict__ rot, const float* __restrict__ cam,
    const float* __restrict__ foc, const float* __restrict__ pp,
    const float* __restrict__ pix, const float* __restrict__ bg,
    float* __restrict__ out) {
  __shared__ uint4 sk[(NSTEPS + 1) * 2];
  for (int i = threadIdx.y * 32 + threadIdx.x; i < (NSTEPS + 1) * 2; i += 128)
    sk[i] = g_keys8[i];
  __syncthreads();

  int x = blockIdx.x * 32 + threadIdx.x;
  int y = blockIdx.y * 4 + threadIdx.y;
  int b = blockIdx.z;
  int p = (b * H_ + y) * W_ + x;

  // ray direction
  float px = pix[(size_t)p * 2 + 0];
  float py = pix[(size_t)p * 2 + 1];
  float vx = (px - pp[b * 2 + 0]) / foc[b * 2 + 0];
  float vy = (py - pp[b * 2 + 1]) / foc[b * 2 + 1];
  const float* R = rot + b * 9;
  float rdx = R[0] * vx + R[3] * vy + R[6];
  float rdy = R[1] * vx + R[4] * vy + R[7];
  float rdz = R[2] * vx + R[5] * vy + R[8];
  float nrm = sqrtf(rdx * rdx + rdy * rdy + rdz * rdz);
  rdx /= nrm; rdy /= nrm; rdz /= nrm;

  float cx = cam[b * 3 + 0], cy = cam[b * 3 + 1], cz = cam[b * 3 + 2];

  // box intersection [-1,1]^3
  float t1x = (-1.0f - cx) / rdx, t2x = (1.0f - cx) / rdx;
  float t1y = (-1.0f - cy) / rdy, t2y = (1.0f - cy) / rdy;
  float t1z = (-1.0f - cz) / rdz, t2z = (1.0f - cz) / rdz;
  float tmin = fmaxf(fminf(t1x, t2x), fmaxf(fminf(t1y, t2y), fminf(t1z, t2z)));
  float tmax = fminf(fmaxf(t1x, t2x), fminf(fmaxf(t1y, t2y), fmaxf(t1z, t2z)));
  bool hit = tmin < tmax;
  float t = fmaxf(hit ? tmin : 0.0f, 0.0f);
  float t_exit = hit ? (tmax + 0.04f) : -1e30f;  // conservative: t>t_exit => pos invalid

  // initial jitter: t -= DT * uniform(fold_in(key,0))
  t = t - 0.02f * bits_to_u01(rbits8(sk[0], sk[1], (unsigned)p));

  // march in grid coordinates: g = (pos + 1) * 63.5, valid <=> g in (0, 127)
  float gx = (cx + rdx * t + 1.0f) * 63.5f;
  float gy = (cy + rdy * t + 1.0f) * 63.5f;
  float gz = (cz + rdz * t + 1.0f) * 63.5f;
  float rgx = rdx * 63.5f, rgy = rdy * 63.5f, rgz = rdz * 63.5f;

  float rr = 0.f, rg = 0.f, rb = 0.f, ra = 0.f, rl = 0.f;
  const float4* __restrict__ grid = g_grid + (size_t)b * NVOX;
  const uint4* kp = sk + 2;  // keys for step 0

  int i = 0;
#pragma unroll 2
  for (; i < NSTEPS; ) {
    float step = step_for(kp, (unsigned)p);
    kp += 2;

    bool active = (ra < 1.0f) &
                  (gx > 0.0f) & (gx < 127.0f) &
                  (gy > 0.0f) & (gy < 127.0f) &
                  (gz > 0.0f) & (gz < 127.0f);

    float contrib = 0.0f;
    if (active) {
      int ix = (int)gx, iy = (int)gy, iz = (int)gz;  // trunc == floor (g > 0)
      float wx = gx - (float)ix, wy = gy - (float)iy, wz = gz - (float)iz;
      float ox = 1.0f - wx, oy = 1.0f - wy, oz = 1.0f - wz;
      float w00 = ox * oy, w10 = wx * oy, w01 = ox * wy, w11 = wx * wy;
      float v000 = w00 * oz, v100 = w10 * oz, v010 = w01 * oz, v110 = w11 * oz;
      float v001 = w00 * wz, v101 = w10 * wz, v011 = w01 * wz, v111 = w11 * wz;

      const float4* base = grid + ((iz * D_ + iy) * D_ + ix);
      float4 a000 = __ldg(base);
      float4 a100 = __ldg(base + 1);
      float4 a010 = __ldg(base + D_);
      float4 a110 = __ldg(base + D_ + 1);
      float4 a001 = __ldg(base + D_ * D_);
      float4 a101 = __ldg(base + D_ * D_ + 1);
      float4 a011 = __ldg(base + D_ * D_ + D_);
      float4 a111 = __ldg(base + D_ * D_ + D_ + 1);

      float sxr = v000 * a000.x, sxg = v000 * a000.y, sxb = v000 * a000.z, sxa = v000 * a000.w;
      sxr = fmaf(v100, a100.x, sxr); sxg = fmaf(v100, a100.y, sxg);
      sxb = fmaf(v100, a100.z, sxb); sxa = fmaf(v100, a100.w, sxa);
      sxr = fmaf(v010, a010.x, sxr); sxg = fmaf(v010, a010.y, sxg);
      sxb = fmaf(v010, a010.z, sxb); sxa = fmaf(v010, a010.w, sxa);
      sxr = fmaf(v110, a110.x, sxr); sxg = fmaf(v110, a110.y, sxg);
      sxb = fmaf(v110, a110.z, sxb); sxa = fmaf(v110, a110.w, sxa);
      sxr = fmaf(v001, a001.x, sxr); sxg = fmaf(v001, a001.y, sxg);
      sxb = fmaf(v001, a001.z, sxb); sxa = fmaf(v001, a001.w, sxa);
      sxr = fmaf(v101, a101.x, sxr); sxg = fmaf(v101, a101.y, sxg);
      sxb = fmaf(v101, a101.z, sxb); sxa = fmaf(v101, a101.w, sxa);
      sxr = fmaf(v011, a011.x, sxr); sxg = fmaf(v011, a011.y, sxg);
      sxb = fmaf(v011, a011.z, sxb); sxa = fmaf(v011, a011.w, sxa);
      sxr = fmaf(v111, a111.x, sxr); sxg = fmaf(v111, a111.y, sxg);
      sxb = fmaf(v111, a111.z, sxb); sxa = fmaf(v111, a111.w, sxa);

      contrib = fminf(fmaf(sxa, step, ra), 1.0f) - ra;
      rr = fmaf(sxr, contrib, rr);
      rg = fmaf(sxg, contrib, rg);
      rb = fmaf(sxb, contrib, rb);
      ra += contrib;
    }
    if (contrib == 0.0f) rl += step;

    gx = fmaf(rgx, step, gx);
    gy = fmaf(rgy, step, gy);
    gz = fmaf(rgz, step, gz);
    t += step;
    i++;

    // terminal: past box exit (convex, never re-enters) or alpha saturated exactly.
    if (__all_sync(0xFFFFFFFFu, (t > t_exit) | (ra >= 1.0f))) break;
  }

  // tail: contrib identically 0; only ray_length accumulates.
  // Unroll x4: batched key loads + 4 independent accumulator chains.
  float rl0 = 0.0f, rl1 = 0.0f, rl2 = 0.0f, rl3 = 0.0f;
#pragma unroll 1
  for (; i + 4 <= NSTEPS; i += 4) {
    uint4 a0 = kp[0], b0 = kp[1], a1 = kp[2], b1 = kp[3];
    uint4 a2 = kp[4], b2 = kp[5], a3 = kp[6], b3 = kp[7];
    kp += 8;
    rl0 += jitter_step_tail(bits_to_u(rbits8(a0, b0, (unsigned)p)));
    rl1 += jitter_step_tail(bits_to_u(rbits8(a1, b1, (unsigned)p)));
    rl2 += jitter_step_tail(bits_to_u(rbits8(a2, b2, (unsigned)p)));
    rl3 += jitter_step_tail(bits_to_u(rbits8(a3, b3, (unsigned)p)));
  }
#pragma unroll 1
  for (; i < NSTEPS; i++) {
    rl0 += jitter_step_tail(bits_to_u(rbits8(kp[0], kp[1], (unsigned)p)));
    kp += 2;
  }
  rl += (rl0 + rl1) + (rl2 + rl3);

  // compositing with background
  float b0f = fmaxf(bg[((size_t)(b * 3 + 0) * H_ + y) * W_ + x], 0.0f);
  float b1f = fmaxf(bg[((size_t)(b * 3 + 1) * H_ + y) * W_ + x], 0.0f);
  float b2f = fmaxf(bg[((size_t)(b * 3 + 2) * H_ + y) * W_ + x], 0.0f);
  float om = 1.0f - ra;
  out[((size_t)(b * 3 + 0) * H_ + y) * W_ + x] = rr + om * b0f;
  out[((size_t)(b * 3 + 1) * H_ + y) * W_ + x] = rg + om * b1f;
  out[((size_t)(b * 3 + 2) * H_ + y) * W_ + x] = rb + om * b2f;
  out[A_OFF + p] = ra;
  out[L_OFF + p] = rl;  // raw; normalized by finalize_kernel

  // block min/max reduction of rl (>= 0, so uint order == float order)
  unsigned lb = __float_as_uint(rl);
  unsigned mn = lb, mx = lb;
#pragma unroll
  for (int o = 16; o; o >>= 1) {
    mn = min(mn, __shfl_xor_sync(0xFFFFFFFFu, mn, o));
    mx = max(mx, __shfl_xor_sync(0xFFFFFFFFu, mx, o));
  }
  __shared__ unsigned smn[4], smx[4];
  if (threadIdx.x == 0) { smn[threadIdx.y] = mn; smx[threadIdx.y] = mx; }
  __syncthreads();
  if (threadIdx.x == 0 && threadIdx.y == 0) {
    mn = min(min(smn[0], smn[1]), min(smn[2], smn[3]));
    mx = max(max(smx[0], smx[1]), max(smx[2], smx[3]));
    atomicMin(&g_minb, mn);
    atomicMax(&g_maxb, mx);
  }
}

__global__ void finalize_kernel(float* __restrict__ out) {
  int p = blockIdx.x * blockDim.x + threadIdx.x;
  if (p >= NPIX) return;
  float denom = __uint_as_float(g_maxb) + __uint_as_float(g_minb);
  out[L_OFF + p] = out[A_OFF + p] * out[L_OFF + p] / denom;
}

// ---------------- launch ----------------
extern "C" void kernel_launch(void* const* d_in, const int* in_sizes, int n_in,
                              void* d_out, int out_size) {
  const float* rot = (const float*)d_in[0];  // camera_rotation (B,3,3)
  const float* cam = (const float*)d_in[1];  // camera_position (B,3)
  const float* foc = (const float*)d_in[2];  // focal (B,2)
  const float* pp  = (const float*)d_in[3];  // principal_point (B,2)
  const float* pix = (const float*)d_in[4];  // pixel_coords (B,H,W,2)
  const float* tpl = (const float*)d_in[5];  // template (B,4,D,D,D)
  const float* bg  = (const float*)d_in[6];  // background (B,3,H,W)
  float* out = (float*)d_out;

  init_kernel<<<1, 256>>>();
  transpose_kernel<<<(B_ * NVOX + 255) / 256, 256>>>(tpl);
  dim3 blk(32, 4, 1);
  dim3 grd(W_ / 32, H_ / 4, B_);
  march_kernel<<<grd, blk>>>(rot, cam, foc, pp, pix, bg, out);
  finalize_kernel<<<(NPIX + 255) / 256, 256>>>(out);
}